// round 2
// baseline (speedup 1.0000x reference)
#include <cuda_runtime.h>
#include <stdint.h>

// Problem constants (fixed shapes for torch_shift_82489141887540)
// Input  x: (B=4, C=40, D=64, H=66, W=64) float32
// Output  : (B=4, C2=160, D=64, Hp=17, W=64) float32  +  1 scalar (pad_1=2)
#define B_   4
#define C_   40
#define D_   64
#define H_   66
#define W_   64
#define C2_  160   // C*PIXEL
#define HP_  17    // (H + pad_1) / PIXEL
#define PAD_1 2

// derived strides (in elements)
#define IN_H_STRIDE   (W_)            // 64
#define IN_D_STRIDE   (H_ * W_)       // 4224
#define IN_C_STRIDE   (D_ * H_ * W_)  // 270336
#define IN_B_STRIDE   (C_ * D_ * H_ * W_)

#define OUT_TOTAL     (B_ * C2_ * D_ * HP_ * W_)   // 44,564,480
#define ROWS_TOTAL    (B_ * C2_ * D_ * HP_)        // 696,320 rows of 64 floats

// Each block: 256 threads = 16 rows x 16 float4-lanes.
// Each thread gathers/stores one float4 (16 bytes) -> fully coalesced both sides.
__global__ __launch_bounds__(256) void torch_shift_kernel(
    const float* __restrict__ in, float* __restrict__ out, int out_size)
{
    const int lane = threadIdx.x & 15;                 // w4 index: 0..15
    const int row  = blockIdx.x * 16 + (threadIdx.x >> 4);
    if (row >= ROWS_TOTAL) return;

    // decompose row -> (b, c2, d, hp)
    int t  = row;
    const int hp = t % HP_;  t /= HP_;
    const int d  = t % D_;   t /= D_;
    const int c2 = t % C2_;
    const int b  = t / C2_;

    // index map
    const int p = c2 & 3;
    const int c = c2 >> 2;
    const int j = (c2 % 40) >> 3;          // shift group 0..4
    const int d_src = d + 2 - j;           // static slice of zero-padded D
    int h = hp * 4 + p;
    if (h >= H_) h -= H_;                  // circular pad along H

    float4 v = make_float4(0.f, 0.f, 0.f, 0.f);
    if ((unsigned)d_src < (unsigned)D_) {
        const long long iidx = (long long)b * IN_B_STRIDE
                             + (long long)c * IN_C_STRIDE
                             + (long long)d_src * IN_D_STRIDE
                             + (long long)h * IN_H_STRIDE
                             + lane * 4;
        v = *reinterpret_cast<const float4*>(in + iidx);
    }

    const long long oidx = (long long)row * W_ + lane * 4;
    *reinterpret_cast<float4*>(out + oidx) = v;

    // append pad_1 scalar as a float value (harness compares the tail slot as float32)
    if (row == 0 && lane == 0 && out_size > OUT_TOTAL) {
        out[OUT_TOTAL] = (float)PAD_1;
    }
}

extern "C" void kernel_launch(void* const* d_in, const int* in_sizes, int n_in,
                              void* d_out, int out_size)
{
    const float* x = (const float*)d_in[0];
    float* out = (float*)d_out;

    const int rows_per_block = 16;
    const int blocks = (ROWS_TOTAL + rows_per_block - 1) / rows_per_block; // 43,520
    torch_shift_kernel<<<blocks, 256>>>(x, out, out_size);
}

// round 3
// speedup vs baseline: 1.0005x; 1.0005x over previous
#include <cuda_runtime.h>
#include <stdint.h>

// Problem constants (fixed shapes for torch_shift_82489141887540)
// Input  x: (B=4, C=40, D=64, H=66, W=64) float32
// Output  : (B=4, C2=160, D=64, Hp=17, W=64) float32  +  1 scalar (pad_1=2)
#define B_   4
#define C_   40
#define D_   64
#define H_   66
#define W_   64
#define C2_  160   // C*PIXEL
#define HP_  17    // (H + pad_1) / PIXEL
#define PAD_1 2

#define IN_H_STRIDE   (W_)            // 64
#define IN_D_STRIDE   (H_ * W_)       // 4224
#define IN_C_STRIDE   (D_ * H_ * W_)  // 270336
#define IN_B_STRIDE   (C_ * D_ * H_ * W_)

#define OUT_PLANE     (HP_ * W_)      // 1088 floats per (b,c2,d) plane
#define OUT_TOTAL     (B_ * C2_ * D_ * HP_ * W_)   // 44,564,480

#define D_CHUNK 16                    // d values per block (4 chunks cover D=64)

// grid = (B*C2, D/D_CHUNK) = (640, 4); block = 272 threads = 17 hp x 16 float4-lanes.
// Each thread owns a fixed (b, c2, hp, lane) and walks D_CHUNK d-planes:
// index math once, then pure constant-stride LDG.128/STG.128.
__global__ __launch_bounds__(272) void torch_shift_kernel(
    const float* __restrict__ in, float* __restrict__ out, int out_size)
{
    const int blk  = blockIdx.x;            // 0..639 : b*C2 + c2
    const int b    = blk / C2_;
    const int c2   = blk % C2_;
    const int q    = threadIdx.x;           // 0..271
    const int hp   = q >> 4;                // 0..16
    const int lane = q & 15;                // float4 lane in W

    // block-uniform index map
    const int p = c2 & 3;
    const int c = c2 >> 2;
    const int j = (c2 % 40) >> 3;           // shift group 0..4 (uniform per block)
    int h = hp * 4 + p;
    if (h >= H_) h -= H_;                   // circular pad along H

    // d_src = d + 2 - j ; valid output d range: [max(0, j-2), min(D, 62+j))
    const int d0   = blockIdx.y * D_CHUNK;
    const int d_lo = max(d0,            j - 2);
    const int d_hi = min(d0 + D_CHUNK,  D_ - 2 + j);

    const float* src = in
        + (long long)b * IN_B_STRIDE
        + (long long)c * IN_C_STRIDE
        + (long long)(2 - j) * IN_D_STRIDE   // fold shift into base; only deref'd when valid
        + h * IN_H_STRIDE + lane * 4;
    float* dst = out
        + (long long)blk * (D_ * OUT_PLANE)
        + hp * W_ + lane * 4;

    const float4 z = make_float4(0.f, 0.f, 0.f, 0.f);

    // leading zero planes (at most 2, only when j>2 and d0==0)
    for (int d = d0; d < d_lo; ++d)
        *reinterpret_cast<float4*>(dst + (long long)d * OUT_PLANE) = z;

    // hot loop: pure strided copy
    #pragma unroll 8
    for (int d = d_lo; d < d_hi; ++d)
        *reinterpret_cast<float4*>(dst + (long long)d * OUT_PLANE) =
            *reinterpret_cast<const float4*>(src + (long long)d * IN_D_STRIDE);

    // trailing zero planes (at most 2, only when j<2 and last chunk)
    for (int d = max(d_lo, d_hi); d < d0 + D_CHUNK; ++d)
        *reinterpret_cast<float4*>(dst + (long long)d * OUT_PLANE) = z;

    // append pad_1 scalar as float (harness compares tail slot as float32)
    if (blk == 0 && q == 0 && blockIdx.y == 0 && out_size > OUT_TOTAL)
        out[OUT_TOTAL] = (float)PAD_1;
}

extern "C" void kernel_launch(void* const* d_in, const int* in_sizes, int n_in,
                              void* d_out, int out_size)
{
    const float* x = (const float*)d_in[0];
    float* out = (float*)d_out;

    dim3 grid(B_ * C2_, D_ / D_CHUNK);   // (640, 4)
    torch_shift_kernel<<<grid, 272>>>(x, out, out_size);
}